// round 10
// baseline (speedup 1.0000x reference)
#include <cuda_runtime.h>
#include <cuda_bf16.h>

#define KS 7
#define KK 49
#define TPB 64

// Keys bicubic (a=-0.5), branch-free: cubic(x) = u^2(1-2u) + v^2(4v-2),
// u = sat(1-|x|), v = sat(1-|x|/2). C1-continuous, EXACTLY zero for |x|>=2.
__device__ __forceinline__ float cubic_w(float x) {
    float ax = fabsf(x);
    float u = __saturatef(1.0f - ax);
    float v = __saturatef(fmaf(ax, -0.5f, 1.0f));
    return fmaf(v * v, fmaf(v, 4.0f, -2.0f), (u * u) * fmaf(u, -2.0f, 1.0f));
}

__global__ __launch_bounds__(TPB, 16)
void kest_kernel(const float* __restrict__ m,
                 const float* __restrict__ grid,
                 const int*   __restrict__ Wp,
                 const int*   __restrict__ yi,
                 float*       __restrict__ out,
                 int N)
{
    __shared__ __align__(16) float w_s[TPB * KK];  // NORMALIZED weights, output order

    const int t = threadIdx.x;
    const int lane = t & 31;
    const int warp = t >> 5;
    const int n = blockIdx.x * TPB + t;
    const int n_eff = min(n, N - 1);     // all lanes compute; OOB clamped

    const float m00 = __ldg(m + 0), m01 = __ldg(m + 1), m02 = __ldg(m + 2);
    const float m10 = __ldg(m + 3), m11 = __ldg(m + 4), m12 = __ldg(m + 5);
    const float m20 = __ldg(m + 6), m21 = __ldg(m + 7), m22 = __ldg(m + 8);
    const unsigned W = (unsigned)__ldg(Wp);

    const unsigned p = (unsigned)__ldg(yi + n_eff);
    unsigned pxi, pyi_;
    if ((W & (W - 1u)) == 0u) {          // uniform branch
        const int sh = __ffs((int)W) - 1;
        pxi = p & (W - 1u);
        pyi_ = p >> sh;
    } else {
        pyi_ = p / W;
        pxi = p - pyi_ * W;
    }
    const float px = (float)pxi;
    const float py = (float)pyi_;

    // Analytic central differences of the homography map (algebraically equal
    // to the reference's (pr-pl), (pb-pt) finite differences).
    const float X0 = fmaf(m00, px, fmaf(m01, py, m02));
    const float Y0 = fmaf(m10, px, fmaf(m11, py, m12));
    const float Z0 = fmaf(m20, px, fmaf(m21, py, m22));
    const float Z2 = Z0 * Z0;
    const float da = fmaf(m21, -0.25f * m21, Z2);
    const float db = fmaf(m20, -0.25f * m20, Z2);
    const float rab = __frcp_rn(da * db);
    const float idu = rab * db;
    const float idv = rab * da;

    float du0 = (m01 * Z0 - m21 * X0) * idu;
    float du1 = (m11 * Z0 - m21 * Y0) * idu;
    float dv0 = (m00 * Z0 - m20 * X0) * idv;
    float dv1 = (m10 * Z0 - m20 * Y0) * idv;

    // branch-free |du| >= 1 regularization via rsqrt
    float s  = fmaf(du0, du0, du1 * du1);
    float rs = __frsqrt_rn(s);
    float len = s * rs;
    bool cnd = len < 1.0f;
    float sc = cnd ? rs : 1.0f;
    du0 *= sc; du1 *= sc;
    float rlen_du = cnd ? 1.0f : rs;

    float s2  = fmaf(dv0, dv0, dv1 * dv1);
    float rs2 = __frsqrt_rn(s2);
    float len2 = s2 * rs2;
    bool cnd2 = len2 < 1.0f;
    float sc2 = cnd2 ? rs2 : 1.0f;
    dv0 *= sc2; dv1 *= sc2;
    float rlen_dv = cnd2 ? 1.0f : rs2;

    const float det  = du0 * dv1 - du1 * dv0;
    const float rdet = __frcp_rn(det);
    const float ild  = rdet * rlen_du;
    const float ilv  = rdet * rlen_dv;

    const float Axx = du0 * dv1 * ild - du1 * dv0 * ilv;
    const float Axy = du0 * du1 * (ilv - ild);
    const float Cxx = dv0 * dv1 * (ild - ilv);
    const float Dyy = dv1 * du0 * ilv - dv0 * du1 * ild;

    const float gx = __ldg(grid + n_eff);
    const float gy = __ldg(grid + N + n_eff);
    const float fx = (gx + 0.5f) - floorf(gx + 0.5f);
    const float fy = (gy + 0.5f) - floorf(gy + 0.5f);

    float* wrow = &w_s[t * KK];

    // 5x5 support condition (EXACT, no approximation):
    // taps 0 and 6 have |main arg| >= 0.85*2.5 = 2.125; cross perturbation
    // bounded by 3.5*max(|Axy|,|Cxx|) <= 0.125 keeps |arg| >= 2 -> cubic == 0.
    const float crossmax = fmaxf(fabsf(Axy), fabsf(Cxx)) * 3.5f;
    const bool small = (fabsf(Axx) >= 0.85f) & (fabsf(Dyy) >= 0.85f) & (crossmax <= 0.125f);
    const bool warp_small = __all_sync(0xffffffffu, small);

    if (warp_small) {
        // ---- exact 5x5 core (taps k=1..5 both directions); border exactly 0 ----
        float A[5], Cc[5];
        #pragma unroll
        for (int i = 0; i < 5; i++) {
            float wxk = fx + (1.5f - (float)i);     // k = i+1
            A[i]  = Axx * wxk;
            Cc[i] = Cxx * wxk;
        }

        float w[25];
        float sum0 = 0.0f, sum1 = 0.0f;
        #pragma unroll
        for (int iy = 0; iy < 5; iy++) {
            float wyk = fy + (1.5f - (float)iy);
            float Bk = Axy * wyk;
            float Dk = Dyy * wyk;
            #pragma unroll
            for (int ix = 0; ix < 5; ix++) {
                float v = cubic_w(A[ix] + Bk) * cubic_w(Cc[ix] + Dk);
                w[iy * 5 + ix] = v;
                if (ix & 1) sum1 += v; else sum0 += v;
            }
        }
        const float inv = __frcp_rn(sum0 + sum1);

        // zero border: rows 0,6 and cols 0,6
        #pragma unroll
        for (int j = 0; j < KS; j++) { wrow[j] = 0.0f; wrow[42 + j] = 0.0f; }
        #pragma unroll
        for (int ky = 1; ky <= 5; ky++) { wrow[ky * KS] = 0.0f; wrow[ky * KS + 6] = 0.0f; }

        // store normalized core
        #pragma unroll
        for (int iy = 0; iy < 5; iy++) {
            float* r = wrow + (iy + 1) * KS + 1;
            #pragma unroll
            for (int ix = 0; ix < 5; ix++) {
                r[ix] = w[iy * 5 + ix] * inv;
            }
        }
    } else {
        // ---- exact 7x7 fallback ----
        float A[KS], Cc[KS];
        #pragma unroll
        for (int k = 0; k < KS; k++) {
            float wxk = fx + (2.5f - (float)k);
            A[k]  = Axx * wxk;
            Cc[k] = Cxx * wxk;
        }
        float sum0 = 0.0f, sum1 = 0.0f;
        #pragma unroll
        for (int ky = 0; ky < KS; ky++) {
            float wyk = fy + (2.5f - (float)ky);
            float Bk = Axy * wyk;
            float Dk = Dyy * wyk;
            #pragma unroll
            for (int kx = 0; kx < KS; kx++) {
                float v = cubic_w(A[kx] + Bk) * cubic_w(Cc[kx] + Dk);
                if (kx & 1) sum1 += v; else sum0 += v;
                wrow[ky * KS + kx] = v;
            }
        }
        const float inv = __frcp_rn(sum0 + sum1);
        #pragma unroll
        for (int j = 0; j < KK; j++) wrow[j] *= inv;
    }

    // ---- per-warp write-out: bulk async copy of this warp's 32 rows.
    // wait_group.read: only wait until TMA has READ the SMEM (block may then
    // exit safely); the GMEM commit completes asynchronously.
    __syncwarp();
    const long long blockBase = (long long)blockIdx.x * (TPB * KK);
    const int warpPixBase = blockIdx.x * TPB + warp * 32;
    const int pix = min(32, N - warpPixBase);
    if (pix == 32) {
        if (lane == 0) {
            unsigned saddr = (unsigned)__cvta_generic_to_shared(w_s + warp * 32 * KK);
            asm volatile("fence.proxy.async.shared::cta;" ::: "memory");
            asm volatile("cp.async.bulk.global.shared::cta.bulk_group [%0], [%1], %2;"
                         :: "l"(out + blockBase + warp * 32 * KK), "r"(saddr),
                            "r"((unsigned)(32 * KK * 4))
                         : "memory");
            asm volatile("cp.async.bulk.commit_group;" ::: "memory");
            asm volatile("cp.async.bulk.wait_group.read 0;" ::: "memory");
        }
    } else if (pix > 0) {
        const int cnt = pix * KK;
        const int off = warp * 32 * KK;
        for (int i = lane; i < cnt; i += 32) out[blockBase + off + i] = w_s[off + i];
    }
}

extern "C" void kernel_launch(void* const* d_in, const int* in_sizes, int n_in,
                              void* d_out, int out_size) {
    // metadata order: m_inverse (9), grid (2N), H (1), W (1), yi (N)
    const float* m    = (const float*)d_in[0];
    const float* grid = (const float*)d_in[1];
    const int*   Wp   = (const int*)d_in[3];
    const int*   yi   = (const int*)d_in[4];
    float* out = (float*)d_out;

    const int N = in_sizes[4];
    const int blocks = (N + TPB - 1) / TPB;
    kest_kernel<<<blocks, TPB>>>(m, grid, Wp, yi, out, N);
}

// round 11
// speedup vs baseline: 1.0220x; 1.0220x over previous
#include <cuda_runtime.h>
#include <cuda_bf16.h>

#define KS 7
#define KK 49
#define TPB 128

// Keys bicubic (a=-0.5), branch-free: cubic(x) = u^2(1-2u) + v^2(4v-2),
// u = sat(1-|x|), v = sat(1-|x|/2). C1-continuous, EXACTLY zero for |x|>=2.
__device__ __forceinline__ float cubic_w(float x) {
    float ax = fabsf(x);
    float u = __saturatef(1.0f - ax);
    float v = __saturatef(fmaf(ax, -0.5f, 1.0f));
    return fmaf(v * v, fmaf(v, 4.0f, -2.0f), (u * u) * fmaf(u, -2.0f, 1.0f));
}

__global__ __launch_bounds__(TPB, 10)      // 51-reg cap -> 10 blocks -> 40 warps/SM
void kest_kernel(const float* __restrict__ m,
                 const float* __restrict__ grid,
                 const int*   __restrict__ Wp,
                 const int*   __restrict__ yi,
                 float*       __restrict__ out,
                 int N)
{
    __shared__ __align__(16) float w_s[TPB * KK];

    const int t = threadIdx.x;
    const int lane = t & 31;
    const int warp = t >> 5;
    const int n = blockIdx.x * TPB + t;
    const int n_eff = min(n, N - 1);      // all lanes compute; OOB clamped

    const float m00 = __ldg(m + 0), m01 = __ldg(m + 1), m02 = __ldg(m + 2);
    const float m10 = __ldg(m + 3), m11 = __ldg(m + 4), m12 = __ldg(m + 5);
    const float m20 = __ldg(m + 6), m21 = __ldg(m + 7), m22 = __ldg(m + 8);
    const unsigned W = (unsigned)__ldg(Wp);

    const unsigned p = (unsigned)__ldg(yi + n_eff);
    unsigned pxi, pyi_;
    if ((W & (W - 1u)) == 0u) {           // uniform branch
        const int sh = __ffs((int)W) - 1;
        pxi = p & (W - 1u);
        pyi_ = p >> sh;
    } else {
        pyi_ = p / W;
        pxi = p - pyi_ * W;
    }
    const float px = (float)pxi;
    const float py = (float)pyi_;

    // Analytic central differences of the homography map (algebraically equal
    // to the reference's (pr-pl), (pb-pt) finite differences).
    const float X0 = fmaf(m00, px, fmaf(m01, py, m02));
    const float Y0 = fmaf(m10, px, fmaf(m11, py, m12));
    const float Z0 = fmaf(m20, px, fmaf(m21, py, m22));
    const float Z2 = Z0 * Z0;
    const float da = fmaf(m21, -0.25f * m21, Z2);
    const float db = fmaf(m20, -0.25f * m20, Z2);
    const float rab = __frcp_rn(da * db);
    const float idu = rab * db;
    const float idv = rab * da;

    float du0 = (m01 * Z0 - m21 * X0) * idu;
    float du1 = (m11 * Z0 - m21 * Y0) * idu;
    float dv0 = (m00 * Z0 - m20 * X0) * idv;
    float dv1 = (m10 * Z0 - m20 * Y0) * idv;

    // branch-free |du| >= 1 regularization via rsqrt
    float s  = fmaf(du0, du0, du1 * du1);
    float rs = __frsqrt_rn(s);
    float len = s * rs;
    bool cnd = len < 1.0f;
    float sc = cnd ? rs : 1.0f;
    du0 *= sc; du1 *= sc;
    float rlen_du = cnd ? 1.0f : rs;

    float s2  = fmaf(dv0, dv0, dv1 * dv1);
    float rs2 = __frsqrt_rn(s2);
    float len2 = s2 * rs2;
    bool cnd2 = len2 < 1.0f;
    float sc2 = cnd2 ? rs2 : 1.0f;
    dv0 *= sc2; dv1 *= sc2;
    float rlen_dv = cnd2 ? 1.0f : rs2;

    const float det  = du0 * dv1 - du1 * dv0;
    const float rdet = __frcp_rn(det);
    const float ild  = rdet * rlen_du;
    const float ilv  = rdet * rlen_dv;

    const float Axx = du0 * dv1 * ild - du1 * dv0 * ilv;
    const float Axy = du0 * du1 * (ilv - ild);
    const float Cxx = dv0 * dv1 * (ild - ilv);
    const float Dyy = dv1 * du0 * ilv - dv0 * du1 * ild;

    const float gx = __ldg(grid + n_eff);
    const float gy = __ldg(grid + N + n_eff);
    const float fx = (gx + 0.5f) - floorf(gx + 0.5f);
    const float fy = (gy + 0.5f) - floorf(gy + 0.5f);

    float* wrow = &w_s[t * KK];

    // 5x5 support condition (EXACT): taps 0,6 have |main arg| >= 0.85*2.5 = 2.125;
    // cross perturbation <= 3.5*max(|Axy|,|Cxx|) <= 0.125 keeps |arg| >= 2 -> cubic == 0.
    const float crossmax = fmaxf(fabsf(Axy), fabsf(Cxx)) * 3.5f;
    const bool small = (fabsf(Axx) >= 0.85f) & (fabsf(Dyy) >= 0.85f) & (crossmax <= 0.125f);
    const bool warp_small = __all_sync(0xffffffffu, small);

    if (warp_small) {
        // ---- exact 5x5 core, row-streamed (no w[] array): STS unnormalized ----
        float A[5], Cc[5];
        #pragma unroll
        for (int i = 0; i < 5; i++) {
            float wxk = fx + (1.5f - (float)i);   // k = i+1
            A[i]  = Axx * wxk;
            Cc[i] = Cxx * wxk;
        }

        // zero border: rows 0,6 and cols 0,6
        #pragma unroll
        for (int j = 0; j < KS; j++) { wrow[j] = 0.0f; wrow[42 + j] = 0.0f; }
        #pragma unroll
        for (int ky = 1; ky <= 5; ky++) { wrow[ky * KS] = 0.0f; wrow[ky * KS + 6] = 0.0f; }

        float sum0 = 0.0f, sum1 = 0.0f;
        #pragma unroll
        for (int iy = 0; iy < 5; iy++) {
            float wyk = fy + (1.5f - (float)iy);
            float Bk = Axy * wyk;
            float Dk = Dyy * wyk;
            float* r = wrow + (iy + 1) * KS + 1;
            #pragma unroll
            for (int ix = 0; ix < 5; ix++) {
                float v = cubic_w(A[ix] + Bk) * cubic_w(Cc[ix] + Dk);
                if (ix & 1) sum1 += v; else sum0 += v;
                r[ix] = v;
            }
        }
        const float inv = __frcp_rn(sum0 + sum1);

        // normalize pass over the 25 core slots (LSU-pipe work, frees registers)
        #pragma unroll
        for (int iy = 0; iy < 5; iy++) {
            float* r = wrow + (iy + 1) * KS + 1;
            #pragma unroll
            for (int ix = 0; ix < 5; ix++) r[ix] *= inv;
        }
    } else {
        // ---- exact 7x7 fallback, row-streamed ----
        float A[KS], Cc[KS];
        #pragma unroll
        for (int k = 0; k < KS; k++) {
            float wxk = fx + (2.5f - (float)k);
            A[k]  = Axx * wxk;
            Cc[k] = Cxx * wxk;
        }
        float sum0 = 0.0f, sum1 = 0.0f;
        #pragma unroll
        for (int ky = 0; ky < KS; ky++) {
            float wyk = fy + (2.5f - (float)ky);
            float Bk = Axy * wyk;
            float Dk = Dyy * wyk;
            float* r = wrow + ky * KS;
            #pragma unroll
            for (int kx = 0; kx < KS; kx++) {
                float v = cubic_w(A[kx] + Bk) * cubic_w(Cc[kx] + Dk);
                if (kx & 1) sum1 += v; else sum0 += v;
                r[kx] = v;
            }
        }
        const float inv = __frcp_rn(sum0 + sum1);
        #pragma unroll
        for (int j = 0; j < KK; j++) wrow[j] *= inv;
    }

    // ---- per-warp write-out: bulk async copy of this warp's 32 rows ----
    __syncwarp();
    const long long blockBase = (long long)blockIdx.x * (TPB * KK);
    const int warpPixBase = blockIdx.x * TPB + warp * 32;
    const int pix = min(32, N - warpPixBase);
    if (pix == 32) {
        if (lane == 0) {
            unsigned saddr = (unsigned)__cvta_generic_to_shared(w_s + warp * 32 * KK);
            asm volatile("fence.proxy.async.shared::cta;" ::: "memory");
            asm volatile("cp.async.bulk.global.shared::cta.bulk_group [%0], [%1], %2;"
                         :: "l"(out + blockBase + warp * 32 * KK), "r"(saddr),
                            "r"((unsigned)(32 * KK * 4))
                         : "memory");
            asm volatile("cp.async.bulk.commit_group;" ::: "memory");
            asm volatile("cp.async.bulk.wait_group.read 0;" ::: "memory");
        }
    } else if (pix > 0) {
        const int cnt = pix * KK;
        const int off = warp * 32 * KK;
        for (int i = lane; i < cnt; i += 32) out[blockBase + off + i] = w_s[off + i];
    }
}

extern "C" void kernel_launch(void* const* d_in, const int* in_sizes, int n_in,
                              void* d_out, int out_size) {
    // metadata order: m_inverse (9), grid (2N), H (1), W (1), yi (N)
    const float* m    = (const float*)d_in[0];
    const float* grid = (const float*)d_in[1];
    const int*   Wp   = (const int*)d_in[3];
    const int*   yi   = (const int*)d_in[4];
    float* out = (float*)d_out;

    const int N = in_sizes[4];
    const int blocks = (N + TPB - 1) / TPB;
    kest_kernel<<<blocks, TPB>>>(m, grid, Wp, yi, out, N);
}

// round 12
// speedup vs baseline: 1.3595x; 1.3303x over previous
#include <cuda_runtime.h>
#include <cuda_bf16.h>

#define KS 7
#define KK 49
#define TPB 128
#define MAXBLK (148 * 8)

// Keys bicubic (a=-0.5), branch-free: cubic(x) = u^2(1-2u) + v^2(4v-2),
// u = sat(1-|x|), v = sat(1-|x|/2). C1-continuous, EXACTLY zero for |x|>=2.
__device__ __forceinline__ float cubic_w(float x) {
    float ax = fabsf(x);
    float u = __saturatef(1.0f - ax);
    float v = __saturatef(fmaf(ax, -0.5f, 1.0f));
    return fmaf(v * v, fmaf(v, 4.0f, -2.0f), (u * u) * fmaf(u, -2.0f, 1.0f));
}

__global__ __launch_bounds__(TPB, 8)
void kest_kernel(const float* __restrict__ m,
                 const float* __restrict__ grid,
                 const int*   __restrict__ Wp,
                 const int*   __restrict__ yi,
                 float*       __restrict__ out,
                 int N, int numTiles)
{
    __shared__ __align__(16) float w_s[TPB * KK];

    const int t = threadIdx.x;
    const int lane = t & 31;
    const int warp = t >> 5;

    // loop-invariant loads (once per thread)
    const float m00 = __ldg(m + 0), m01 = __ldg(m + 1), m02 = __ldg(m + 2);
    const float m10 = __ldg(m + 3), m11 = __ldg(m + 4), m12 = __ldg(m + 5);
    const float m20 = __ldg(m + 6), m21 = __ldg(m + 7), m22 = __ldg(m + 8);
    const unsigned W = (unsigned)__ldg(Wp);
    const bool wpow2 = (W & (W - 1u)) == 0u;
    const int wsh = __ffs((int)W) - 1;

    int tile = blockIdx.x;
    if (tile >= numTiles) return;

    // prefetch tile 0 inputs
    int n_eff = min(tile * TPB + t, N - 1);
    unsigned pcur = (unsigned)__ldg(yi + n_eff);
    float gxcur = __ldg(grid + n_eff);
    float gycur = __ldg(grid + N + n_eff);

    while (true) {
        // issue next tile's loads early (hidden behind this tile's compute)
        const int next = tile + gridDim.x;
        unsigned pnext = 0; float gxnext = 0.0f, gynext = 0.0f;
        if (next < numTiles) {
            int n2 = min(next * TPB + t, N - 1);
            pnext = (unsigned)__ldg(yi + n2);
            gxnext = __ldg(grid + n2);
            gynext = __ldg(grid + N + n2);
        }

        // ---- per-pixel setup ----
        unsigned pxi, pyi_;
        if (wpow2) { pxi = pcur & (W - 1u); pyi_ = pcur >> wsh; }
        else       { pyi_ = pcur / W; pxi = pcur - pyi_ * W; }
        const float px = (float)pxi;
        const float py = (float)pyi_;

        // analytic central differences of the homography map
        const float X0 = fmaf(m00, px, fmaf(m01, py, m02));
        const float Y0 = fmaf(m10, px, fmaf(m11, py, m12));
        const float Z0 = fmaf(m20, px, fmaf(m21, py, m22));
        const float Z2 = Z0 * Z0;
        const float da = fmaf(m21, -0.25f * m21, Z2);
        const float db = fmaf(m20, -0.25f * m20, Z2);
        const float rab = __frcp_rn(da * db);
        const float idu = rab * db;
        const float idv = rab * da;

        float du0 = (m01 * Z0 - m21 * X0) * idu;
        float du1 = (m11 * Z0 - m21 * Y0) * idu;
        float dv0 = (m00 * Z0 - m20 * X0) * idv;
        float dv1 = (m10 * Z0 - m20 * Y0) * idv;

        float s  = fmaf(du0, du0, du1 * du1);
        float rs = __frsqrt_rn(s);
        float len = s * rs;
        bool cnd = len < 1.0f;
        float sc = cnd ? rs : 1.0f;
        du0 *= sc; du1 *= sc;
        float rlen_du = cnd ? 1.0f : rs;

        float s2  = fmaf(dv0, dv0, dv1 * dv1);
        float rs2 = __frsqrt_rn(s2);
        float len2 = s2 * rs2;
        bool cnd2 = len2 < 1.0f;
        float sc2 = cnd2 ? rs2 : 1.0f;
        dv0 *= sc2; dv1 *= sc2;
        float rlen_dv = cnd2 ? 1.0f : rs2;

        const float det  = du0 * dv1 - du1 * dv0;
        const float rdet = __frcp_rn(det);
        const float ild  = rdet * rlen_du;
        const float ilv  = rdet * rlen_dv;

        const float Axx = du0 * dv1 * ild - du1 * dv0 * ilv;
        const float Axy = du0 * du1 * (ilv - ild);
        const float Cxx = dv0 * dv1 * (ild - ilv);
        const float Dyy = dv1 * du0 * ilv - dv0 * du1 * ild;

        const float fx = (gxcur + 0.5f) - floorf(gxcur + 0.5f);
        const float fy = (gycur + 0.5f) - floorf(gycur + 0.5f);

        float* wrow = &w_s[t * KK];

        // 5x5 support condition (EXACT): taps 0,6 have |main arg| >= 2.125;
        // cross perturbation <= 0.125 keeps |arg| >= 2 -> cubic == 0.
        const float crossmax = fmaxf(fabsf(Axy), fabsf(Cxx)) * 3.5f;
        const bool small = (fabsf(Axx) >= 0.85f) & (fabsf(Dyy) >= 0.85f) & (crossmax <= 0.125f);
        const bool warp_small = __all_sync(0xffffffffu, small);

        if (warp_small) {
            // ---- exact 5x5 core; border exactly 0 ----
            float A[5], Cc[5];
            #pragma unroll
            for (int i = 0; i < 5; i++) {
                float wxk = fx + (1.5f - (float)i);   // k = i+1
                A[i]  = Axx * wxk;
                Cc[i] = Cxx * wxk;
            }

            float w[25];
            float sum0 = 0.0f, sum1 = 0.0f;
            #pragma unroll
            for (int iy = 0; iy < 5; iy++) {
                float wyk = fy + (1.5f - (float)iy);
                float Bk = Axy * wyk;
                float Dk = Dyy * wyk;
                #pragma unroll
                for (int ix = 0; ix < 5; ix++) {
                    float v = cubic_w(A[ix] + Bk) * cubic_w(Cc[ix] + Dk);
                    w[iy * 5 + ix] = v;
                    if (ix & 1) sum1 += v; else sum0 += v;
                }
            }
            const float inv = __frcp_rn(sum0 + sum1);

            // zero border: rows 0,6 and cols 0,6
            #pragma unroll
            for (int j = 0; j < KS; j++) { wrow[j] = 0.0f; wrow[42 + j] = 0.0f; }
            #pragma unroll
            for (int ky = 1; ky <= 5; ky++) { wrow[ky * KS] = 0.0f; wrow[ky * KS + 6] = 0.0f; }

            #pragma unroll
            for (int iy = 0; iy < 5; iy++) {
                float* r = wrow + (iy + 1) * KS + 1;
                #pragma unroll
                for (int ix = 0; ix < 5; ix++) r[ix] = w[iy * 5 + ix] * inv;
            }
        } else {
            // ---- exact 7x7 fallback ----
            float A[KS], Cc[KS];
            #pragma unroll
            for (int k = 0; k < KS; k++) {
                float wxk = fx + (2.5f - (float)k);
                A[k]  = Axx * wxk;
                Cc[k] = Cxx * wxk;
            }
            float sum0 = 0.0f, sum1 = 0.0f;
            #pragma unroll
            for (int ky = 0; ky < KS; ky++) {
                float wyk = fy + (2.5f - (float)ky);
                float Bk = Axy * wyk;
                float Dk = Dyy * wyk;
                float* r = wrow + ky * KS;
                #pragma unroll
                for (int kx = 0; kx < KS; kx++) {
                    float v = cubic_w(A[kx] + Bk) * cubic_w(Cc[kx] + Dk);
                    if (kx & 1) sum1 += v; else sum0 += v;
                    r[kx] = v;
                }
            }
            const float inv = __frcp_rn(sum0 + sum1);
            #pragma unroll
            for (int j = 0; j < KK; j++) wrow[j] *= inv;
        }

        // ---- per-warp write-out: bulk async copy of this warp's 32 rows ----
        __syncwarp();
        const long long blockBase = (long long)tile * (TPB * KK);
        const int warpPixBase = tile * TPB + warp * 32;
        const int pix = min(32, N - warpPixBase);
        if (pix == 32) {
            if (lane == 0) {
                unsigned saddr = (unsigned)__cvta_generic_to_shared(w_s + warp * 32 * KK);
                asm volatile("fence.proxy.async.shared::cta;" ::: "memory");
                asm volatile("cp.async.bulk.global.shared::cta.bulk_group [%0], [%1], %2;"
                             :: "l"(out + blockBase + warp * 32 * KK), "r"(saddr),
                                "r"((unsigned)(32 * KK * 4))
                             : "memory");
                asm volatile("cp.async.bulk.commit_group;" ::: "memory");
                asm volatile("cp.async.bulk.wait_group.read 0;" ::: "memory");
            }
        } else if (pix > 0) {
            const int cnt = pix * KK;
            const int off = warp * 32 * KK;
            for (int i = lane; i < cnt; i += 32) out[blockBase + off + i] = w_s[off + i];
        }
        // all lanes must see the TMA SMEM-read complete before next iteration overwrites
        __syncwarp();

        if (next >= numTiles) break;
        tile = next;
        pcur = pnext; gxcur = gxnext; gycur = gynext;
    }
}

extern "C" void kernel_launch(void* const* d_in, const int* in_sizes, int n_in,
                              void* d_out, int out_size) {
    // metadata order: m_inverse (9), grid (2N), H (1), W (1), yi (N)
    const float* m    = (const float*)d_in[0];
    const float* grid = (const float*)d_in[1];
    const int*   Wp   = (const int*)d_in[3];
    const int*   yi   = (const int*)d_in[4];
    float* out = (float*)d_out;

    const int N = in_sizes[4];
    const int numTiles = (N + TPB - 1) / TPB;
    const int blocks = numTiles < MAXBLK ? numTiles : MAXBLK;
    kest_kernel<<<blocks, TPB>>>(m, grid, Wp, yi, out, N, numTiles);
}

// round 13
// speedup vs baseline: 1.4113x; 1.0381x over previous
#include <cuda_runtime.h>
#include <cuda_bf16.h>

#define KS 7
#define KK 49
#define TPB 128
#define PIX 124   // pixels per block: 124*49*4 = 24304 B <= 24576 (3 x 8KB granules)

// Keys bicubic (a=-0.5), branch-free: cubic(x) = u^2(1-2u) + v^2(4v-2),
// u = sat(1-|x|), v = sat(1-|x|/2). C1-continuous, EXACTLY zero for |x|>=2.
__device__ __forceinline__ float cubic_w(float x) {
    float ax = fabsf(x);
    float u = __saturatef(1.0f - ax);
    float v = __saturatef(fmaf(ax, -0.5f, 1.0f));
    return fmaf(v * v, fmaf(v, 4.0f, -2.0f), (u * u) * fmaf(u, -2.0f, 1.0f));
}

__global__ __launch_bounds__(TPB, 9)   // 9 blocks/SM -> 36 warps, reg cap 56
void kest_kernel(const float* __restrict__ m,
                 const float* __restrict__ grid,
                 const int*   __restrict__ Wp,
                 const int*   __restrict__ yi,
                 float*       __restrict__ out,
                 int N)
{
    __shared__ __align__(16) float w_s[PIX * KK];   // 24304 bytes

    const int t = threadIdx.x;
    const int lane = t & 31;
    const int warp = t >> 5;
    const int n = blockIdx.x * PIX + t;
    const bool active = (t < PIX) && (n < N);
    const int n_eff = min(n, N - 1);      // all lanes compute; keeps warp vote uniform

    const float m00 = __ldg(m + 0), m01 = __ldg(m + 1), m02 = __ldg(m + 2);
    const float m10 = __ldg(m + 3), m11 = __ldg(m + 4), m12 = __ldg(m + 5);
    const float m20 = __ldg(m + 6), m21 = __ldg(m + 7), m22 = __ldg(m + 8);
    const unsigned W = (unsigned)__ldg(Wp);

    const unsigned p = (unsigned)__ldg(yi + n_eff);
    unsigned pxi, pyi_;
    if ((W & (W - 1u)) == 0u) {           // uniform branch
        const int sh = __ffs((int)W) - 1;
        pxi = p & (W - 1u);
        pyi_ = p >> sh;
    } else {
        pyi_ = p / W;
        pxi = p - pyi_ * W;
    }
    const float px = (float)pxi;
    const float py = (float)pyi_;

    // Analytic central differences of the homography map (algebraically equal
    // to the reference's (pr-pl), (pb-pt) finite differences).
    const float X0 = fmaf(m00, px, fmaf(m01, py, m02));
    const float Y0 = fmaf(m10, px, fmaf(m11, py, m12));
    const float Z0 = fmaf(m20, px, fmaf(m21, py, m22));
    const float Z2 = Z0 * Z0;
    const float da = fmaf(m21, -0.25f * m21, Z2);
    const float db = fmaf(m20, -0.25f * m20, Z2);
    const float rab = __frcp_rn(da * db);
    const float idu = rab * db;
    const float idv = rab * da;

    float du0 = (m01 * Z0 - m21 * X0) * idu;
    float du1 = (m11 * Z0 - m21 * Y0) * idu;
    float dv0 = (m00 * Z0 - m20 * X0) * idv;
    float dv1 = (m10 * Z0 - m20 * Y0) * idv;

    // branch-free |du| >= 1 regularization via rsqrt
    float s  = fmaf(du0, du0, du1 * du1);
    float rs = __frsqrt_rn(s);
    float len = s * rs;
    bool cnd = len < 1.0f;
    float sc = cnd ? rs : 1.0f;
    du0 *= sc; du1 *= sc;
    float rlen_du = cnd ? 1.0f : rs;

    float s2  = fmaf(dv0, dv0, dv1 * dv1);
    float rs2 = __frsqrt_rn(s2);
    float len2 = s2 * rs2;
    bool cnd2 = len2 < 1.0f;
    float sc2 = cnd2 ? rs2 : 1.0f;
    dv0 *= sc2; dv1 *= sc2;
    float rlen_dv = cnd2 ? 1.0f : rs2;

    const float det  = du0 * dv1 - du1 * dv0;
    const float rdet = __frcp_rn(det);
    const float ild  = rdet * rlen_du;
    const float ilv  = rdet * rlen_dv;

    const float Axx = du0 * dv1 * ild - du1 * dv0 * ilv;
    const float Axy = du0 * du1 * (ilv - ild);
    const float Cxx = dv0 * dv1 * (ild - ilv);
    const float Dyy = dv1 * du0 * ilv - dv0 * du1 * ild;

    const float gx = __ldg(grid + n_eff);
    const float gy = __ldg(grid + N + n_eff);
    const float fx = (gx + 0.5f) - floorf(gx + 0.5f);
    const float fy = (gy + 0.5f) - floorf(gy + 0.5f);

    float* wrow = &w_s[min(t, PIX - 1) * KK];

    // 5x5 support condition (EXACT): taps 0,6 have |main arg| >= 0.85*2.5 = 2.125;
    // cross perturbation <= 3.5*max(|Axy|,|Cxx|) <= 0.125 keeps |arg| >= 2 -> cubic == 0.
    const float crossmax = fmaxf(fabsf(Axy), fabsf(Cxx)) * 3.5f;
    const bool small = (fabsf(Axx) >= 0.85f) & (fabsf(Dyy) >= 0.85f) & (crossmax <= 0.125f);
    const bool warp_small = __all_sync(0xffffffffu, small);

    if (warp_small) {
        // ---- exact 5x5 core (taps k=1..5 both directions); border exactly 0 ----
        float A[5], Cc[5];
        #pragma unroll
        for (int i = 0; i < 5; i++) {
            float wxk = fx + (1.5f - (float)i);   // k = i+1
            A[i]  = Axx * wxk;
            Cc[i] = Cxx * wxk;
        }

        float w[25];
        float sum0 = 0.0f, sum1 = 0.0f;
        #pragma unroll
        for (int iy = 0; iy < 5; iy++) {
            float wyk = fy + (1.5f - (float)iy);
            float Bk = Axy * wyk;
            float Dk = Dyy * wyk;
            #pragma unroll
            for (int ix = 0; ix < 5; ix++) {
                float v = cubic_w(A[ix] + Bk) * cubic_w(Cc[ix] + Dk);
                w[iy * 5 + ix] = v;
                if (ix & 1) sum1 += v; else sum0 += v;
            }
        }
        const float inv = __frcp_rn(sum0 + sum1);

        if (active) {
            // zero border: rows 0,6 and cols 0,6
            #pragma unroll
            for (int j = 0; j < KS; j++) { wrow[j] = 0.0f; wrow[42 + j] = 0.0f; }
            #pragma unroll
            for (int ky = 1; ky <= 5; ky++) { wrow[ky * KS] = 0.0f; wrow[ky * KS + 6] = 0.0f; }

            #pragma unroll
            for (int iy = 0; iy < 5; iy++) {
                float* r = wrow + (iy + 1) * KS + 1;
                #pragma unroll
                for (int ix = 0; ix < 5; ix++) r[ix] = w[iy * 5 + ix] * inv;
            }
        }
    } else {
        // ---- exact 7x7 fallback ----
        float A[KS], Cc[KS];
        #pragma unroll
        for (int k = 0; k < KS; k++) {
            float wxk = fx + (2.5f - (float)k);
            A[k]  = Axx * wxk;
            Cc[k] = Cxx * wxk;
        }
        float sum0 = 0.0f, sum1 = 0.0f;
        #pragma unroll
        for (int ky = 0; ky < KS; ky++) {
            float wyk = fy + (2.5f - (float)ky);
            float Bk = Axy * wyk;
            float Dk = Dyy * wyk;
            #pragma unroll
            for (int kx = 0; kx < KS; kx++) {
                float v = cubic_w(A[kx] + Bk) * cubic_w(Cc[kx] + Dk);
                if (kx & 1) sum1 += v; else sum0 += v;
                if (active) wrow[ky * KS + kx] = v;
            }
        }
        const float inv = __frcp_rn(sum0 + sum1);
        if (active) {
            #pragma unroll
            for (int j = 0; j < KK; j++) wrow[j] *= inv;
        }
    }

    // ---- per-warp write-out: bulk async copy of this warp's rows ----
    // warps 0-2 own 32 pixels each; warp 3 owns 28 (t = 96..123).
    __syncwarp();
    const int myRows = (warp < 3) ? 32 : (PIX - 96);             // 32 or 28
    const int warpPixBase = blockIdx.x * PIX + warp * 32;
    const long long gBase = (long long)blockIdx.x * PIX * KK + warp * 32 * KK;
    const int pix = min(myRows, N - warpPixBase);
    if (pix == myRows) {
        if (lane == 0) {
            unsigned saddr = (unsigned)__cvta_generic_to_shared(w_s + warp * 32 * KK);
            asm volatile("fence.proxy.async.shared::cta;" ::: "memory");
            asm volatile("cp.async.bulk.global.shared::cta.bulk_group [%0], [%1], %2;"
                         :: "l"(out + gBase), "r"(saddr),
                            "r"((unsigned)(myRows * KK * 4))
                         : "memory");
            asm volatile("cp.async.bulk.commit_group;" ::: "memory");
            asm volatile("cp.async.bulk.wait_group.read 0;" ::: "memory");
        }
    } else if (pix > 0) {
        const int cnt = pix * KK;
        const int off = warp * 32 * KK;
        for (int i = lane; i < cnt; i += 32) out[gBase + i] = w_s[off + i];
    }
}

extern "C" void kernel_launch(void* const* d_in, const int* in_sizes, int n_in,
                              void* d_out, int out_size) {
    // metadata order: m_inverse (9), grid (2N), H (1), W (1), yi (N)
    const float* m    = (const float*)d_in[0];
    const float* grid = (const float*)d_in[1];
    const int*   Wp   = (const int*)d_in[3];
    const int*   yi   = (const int*)d_in[4];
    float* out = (float*)d_out;

    const int N = in_sizes[4];
    const int blocks = (N + PIX - 1) / PIX;
    kest_kernel<<<blocks, TPB>>>(m, grid, Wp, yi, out, N);
}

// round 14
// speedup vs baseline: 1.4690x; 1.0409x over previous
#include <cuda_runtime.h>
#include <cuda_bf16.h>

#define KS 7
#define KK 49
#define TPB 128

// Keys bicubic (a=-0.5), branch-free: cubic(x) = u^2(1-2u) + v^2(4v-2),
// u = sat(1-|x|), v = sat(1-|x|/2). C1-continuous, EXACTLY zero for |x|>=2.
__device__ __forceinline__ float cubic_w(float x) {
    float ax = fabsf(x);
    float u = __saturatef(1.0f - ax);
    float v = __saturatef(fmaf(ax, -0.5f, 1.0f));
    return fmaf(v * v, fmaf(v, 4.0f, -2.0f), (u * u) * fmaf(u, -2.0f, 1.0f));
}

// Evaluate taps kx in [KX0, KX0+KXN), ky in [KY0, KY0+KYN); all other slots are
// provably zero (|arg| >= 2). Exact math, normalized output into wrow[49].
template<int KX0, int KXN, int KY0, int KYN>
__device__ __forceinline__ void eval_tile(float Axx, float Axy, float Cxx, float Dyy,
                                          float fx, float fy, float* wrow)
{
    float A[KXN], Cc[KXN];
    #pragma unroll
    for (int i = 0; i < KXN; i++) {
        float wxk = fx + (2.5f - (float)(KX0 + i));
        A[i]  = Axx * wxk;
        Cc[i] = Cxx * wxk;
    }

    // zero the excluded border slots
    #pragma unroll
    for (int ky = 0; ky < KS; ky++) {
        #pragma unroll
        for (int kx = 0; kx < KS; kx++) {
            if (ky < KY0 || ky >= KY0 + KYN || kx < KX0 || kx >= KX0 + KXN)
                wrow[ky * KS + kx] = 0.0f;
        }
    }

    if constexpr (KXN * KYN <= 25) {
        // register-buffered: store normalized directly
        float w[KXN * KYN];
        float sum0 = 0.0f, sum1 = 0.0f;
        #pragma unroll
        for (int iy = 0; iy < KYN; iy++) {
            float wyk = fy + (2.5f - (float)(KY0 + iy));
            float Bk = Axy * wyk;
            float Dk = Dyy * wyk;
            #pragma unroll
            for (int ix = 0; ix < KXN; ix++) {
                float v = cubic_w(A[ix] + Bk) * cubic_w(Cc[ix] + Dk);
                w[iy * KXN + ix] = v;
                if (ix & 1) sum1 += v; else sum0 += v;
            }
        }
        const float inv = __frcp_rn(sum0 + sum1);
        #pragma unroll
        for (int iy = 0; iy < KYN; iy++) {
            float* r = wrow + (KY0 + iy) * KS + KX0;
            #pragma unroll
            for (int ix = 0; ix < KXN; ix++) r[ix] = w[iy * KXN + ix] * inv;
        }
    } else {
        // streamed: store unnormalized, then renormalize the core slots
        float sum0 = 0.0f, sum1 = 0.0f;
        #pragma unroll
        for (int iy = 0; iy < KYN; iy++) {
            float wyk = fy + (2.5f - (float)(KY0 + iy));
            float Bk = Axy * wyk;
            float Dk = Dyy * wyk;
            float* r = wrow + (KY0 + iy) * KS + KX0;
            #pragma unroll
            for (int ix = 0; ix < KXN; ix++) {
                float v = cubic_w(A[ix] + Bk) * cubic_w(Cc[ix] + Dk);
                if (ix & 1) sum1 += v; else sum0 += v;
                r[ix] = v;
            }
        }
        const float inv = __frcp_rn(sum0 + sum1);
        #pragma unroll
        for (int iy = 0; iy < KYN; iy++) {
            float* r = wrow + (KY0 + iy) * KS + KX0;
            #pragma unroll
            for (int ix = 0; ix < KXN; ix++) r[ix] *= inv;
        }
    }
}

__global__ __launch_bounds__(TPB, 8)
void kest_kernel(const float* __restrict__ m,
                 const float* __restrict__ grid,
                 const int*   __restrict__ Wp,
                 const int*   __restrict__ yi,
                 float*       __restrict__ out,
                 int N)
{
    __shared__ __align__(16) float w_s[TPB * KK];

    const int t = threadIdx.x;
    const int lane = t & 31;
    const int warp = t >> 5;
    const int n = blockIdx.x * TPB + t;
    const int n_eff = min(n, N - 1);      // all lanes compute; keeps votes uniform

    const float m00 = __ldg(m + 0), m01 = __ldg(m + 1), m02 = __ldg(m + 2);
    const float m10 = __ldg(m + 3), m11 = __ldg(m + 4), m12 = __ldg(m + 5);
    const float m20 = __ldg(m + 6), m21 = __ldg(m + 7), m22 = __ldg(m + 8);
    const unsigned W = (unsigned)__ldg(Wp);

    const unsigned p = (unsigned)__ldg(yi + n_eff);
    unsigned pxi, pyi_;
    if ((W & (W - 1u)) == 0u) {           // uniform branch
        const int sh = __ffs((int)W) - 1;
        pxi = p & (W - 1u);
        pyi_ = p >> sh;
    } else {
        pyi_ = p / W;
        pxi = p - pyi_ * W;
    }
    const float px = (float)pxi;
    const float py = (float)pyi_;

    // Analytic central differences of the homography map (algebraically equal
    // to the reference's (pr-pl), (pb-pt) finite differences).
    const float X0 = fmaf(m00, px, fmaf(m01, py, m02));
    const float Y0 = fmaf(m10, px, fmaf(m11, py, m12));
    const float Z0 = fmaf(m20, px, fmaf(m21, py, m22));
    const float Z2 = Z0 * Z0;
    const float da = fmaf(m21, -0.25f * m21, Z2);
    const float db = fmaf(m20, -0.25f * m20, Z2);
    const float rab = __frcp_rn(da * db);
    const float idu = rab * db;
    const float idv = rab * da;

    float du0 = (m01 * Z0 - m21 * X0) * idu;
    float du1 = (m11 * Z0 - m21 * Y0) * idu;
    float dv0 = (m00 * Z0 - m20 * X0) * idv;
    float dv1 = (m10 * Z0 - m20 * Y0) * idv;

    // branch-free |du| >= 1 regularization via rsqrt
    float s  = fmaf(du0, du0, du1 * du1);
    float rs = __frsqrt_rn(s);
    float len = s * rs;
    bool cnd = len < 1.0f;
    float sc = cnd ? rs : 1.0f;
    du0 *= sc; du1 *= sc;
    float rlen_du = cnd ? 1.0f : rs;

    float s2  = fmaf(dv0, dv0, dv1 * dv1);
    float rs2 = __frsqrt_rn(s2);
    float len2 = s2 * rs2;
    bool cnd2 = len2 < 1.0f;
    float sc2 = cnd2 ? rs2 : 1.0f;
    dv0 *= sc2; dv1 *= sc2;
    float rlen_dv = cnd2 ? 1.0f : rs2;

    const float det  = du0 * dv1 - du1 * dv0;
    const float rdet = __frcp_rn(det);
    const float ild  = rdet * rlen_du;
    const float ilv  = rdet * rlen_dv;

    const float Axx = du0 * dv1 * ild - du1 * dv0 * ilv;
    const float Axy = du0 * du1 * (ilv - ild);
    const float Cxx = dv0 * dv1 * (ild - ilv);
    const float Dyy = dv1 * du0 * ilv - dv0 * du1 * ild;

    const float gx = __ldg(grid + n_eff);
    const float gy = __ldg(grid + N + n_eff);
    const float fx = (gx + 0.5f) - floorf(gx + 0.5f);
    const float fy = (gy + 0.5f) - floorf(gy + 0.5f);

    float* wrow = &w_s[t * KK];

    // Per-direction EXACT support gates:
    //   cols 0,6 zero  <=  2.5|Axx| - 3.5|Axy| >= 2   (x-arg stays outside (-2,2))
    //   rows 0,6 zero  <=  2.5|Dyy| - 3.5|Cxx| >= 2   (y-arg stays outside (-2,2))
    const bool okx = fmaf(2.5f, fabsf(Axx), -3.5f * fabsf(Axy)) >= 2.0f;
    const bool oky = fmaf(2.5f, fabsf(Dyy), -3.5f * fabsf(Cxx)) >= 2.0f;
    const bool wx = __all_sync(0xffffffffu, okx);
    const bool wy = __all_sync(0xffffffffu, oky);

    if (wx && wy)      eval_tile<1, 5, 1, 5>(Axx, Axy, Cxx, Dyy, fx, fy, wrow);
    else if (wx)       eval_tile<1, 5, 0, 7>(Axx, Axy, Cxx, Dyy, fx, fy, wrow);
    else if (wy)       eval_tile<0, 7, 1, 5>(Axx, Axy, Cxx, Dyy, fx, fy, wrow);
    else               eval_tile<0, 7, 0, 7>(Axx, Axy, Cxx, Dyy, fx, fy, wrow);

    // ---- per-warp write-out: bulk async copy of this warp's 32 rows ----
    __syncwarp();
    const long long blockBase = (long long)blockIdx.x * (TPB * KK);
    const int warpPixBase = blockIdx.x * TPB + warp * 32;
    const int pix = min(32, N - warpPixBase);
    if (pix == 32) {
        if (lane == 0) {
            unsigned saddr = (unsigned)__cvta_generic_to_shared(w_s + warp * 32 * KK);
            asm volatile("fence.proxy.async.shared::cta;" ::: "memory");
            asm volatile("cp.async.bulk.global.shared::cta.bulk_group [%0], [%1], %2;"
                         :: "l"(out + blockBase + warp * 32 * KK), "r"(saddr),
                            "r"((unsigned)(32 * KK * 4))
                         : "memory");
            asm volatile("cp.async.bulk.commit_group;" ::: "memory");
            asm volatile("cp.async.bulk.wait_group.read 0;" ::: "memory");
        }
    } else if (pix > 0) {
        const int cnt = pix * KK;
        const int off = warp * 32 * KK;
        for (int i = lane; i < cnt; i += 32) out[blockBase + off + i] = w_s[off + i];
    }
}

extern "C" void kernel_launch(void* const* d_in, const int* in_sizes, int n_in,
                              void* d_out, int out_size) {
    // metadata order: m_inverse (9), grid (2N), H (1), W (1), yi (N)
    const float* m    = (const float*)d_in[0];
    const float* grid = (const float*)d_in[1];
    const int*   Wp   = (const int*)d_in[3];
    const int*   yi   = (const int*)d_in[4];
    float* out = (float*)d_out;

    const int N = in_sizes[4];
    const int blocks = (N + TPB - 1) / TPB;
    kest_kernel<<<blocks, TPB>>>(m, grid, Wp, yi, out, N);
}